// round 3
// baseline (speedup 1.0000x reference)
#include <cuda_runtime.h>
#include <cstdint>

// Gate pipeline (2 kernels):
//   K1: conv 4x4/s4 [64,3,512,512]->gate[64,128,128]; last block per batch
//       runs exact K-th-largest radix select, writes d_thr[b]
//   K2: out = in * (gate >= thr ? gate : 0), upsample 4x, bcast 3ch,
//       32B-sector-exact read skipping on dead gate cells (~56% of sectors)
__device__ float    d_gate[64 * 16384];
__device__ unsigned d_thr[64];
__device__ int      d_count[64];   // zero-init; reset by last block each run

__device__ __forceinline__ unsigned f2key(float f) {
    unsigned u = __float_as_uint(f);
    return (u & 0x80000000u) ? ~u : (u | 0x80000000u);  // monotone float->uint
}

// ---------------------------------------------------------------------------
// Kernel 1: conv + fused per-batch top-K threshold select.
// 64 blocks per batch (256 thr each). Last-arriving block per batch does a
// 4-pass MSB-first radix select over the batch's 16384 gate values (L2-hot),
// with warp-aggregated histogram atomics (__match_any_sync) to kill the
// hot-bin contention of the sign/exponent byte.
// ---------------------------------------------------------------------------
__global__ void gate_conv_select_kernel(const float4* __restrict__ in,
                                        const float* __restrict__ wk) {
    __shared__ float4 w[12];
    __shared__ unsigned hist[256];
    __shared__ unsigned s_prefix;
    __shared__ int s_k;
    __shared__ int s_rank;

    const int t = threadIdx.x;
    if (t < 12) w[t] = reinterpret_cast<const float4*>(wk)[t];
    __syncthreads();

    const int idx = blockIdx.x * 256 + t;   // [0, 64*16384); block-uniform batch
    const int x = idx & 127;
    const int y = (idx >> 7) & 127;
    const int b = idx >> 14;

    const float4* base = in + (size_t)b * 196608 + x;
    float sum = 0.0f;
#pragma unroll
    for (int c = 0; c < 3; c++) {
#pragma unroll
        for (int i = 0; i < 4; i++) {
            float4 v = base[c * 65536 + (4 * y + i) * 128];
            float4 ww = w[c * 4 + i];
            sum += v.x * ww.x + v.y * ww.y + v.z * ww.z + v.w * ww.w;
        }
    }
    d_gate[idx] = sum;

    // ---- arrival protocol: last block of this batch runs the select ----
    __threadfence();
    __syncthreads();
    if (t == 0) s_rank = atomicAdd(&d_count[b], 1);
    __syncthreads();
    if (s_rank != 63) return;

    // all 64 blocks of batch b have published their gate values
    const float* grow = d_gate + b * 16384;
    const int lane = t & 31;

    if (t == 0) { s_prefix = 0u; s_k = 4096; }
    __syncthreads();

#pragma unroll
    for (int pass = 0; pass < 4; pass++) {
        const int shift = 24 - 8 * pass;
        hist[t] = 0u;
        __syncthreads();

        const unsigned pmask = pass ? (0xFFFFFFFFu << (32 - 8 * pass)) : 0u;
        const unsigned prefix = s_prefix;

#pragma unroll 4
        for (int i = 0; i < 64; i++) {
            unsigned u = f2key(grow[t + i * 256]);
            unsigned bin = ((u & pmask) == prefix) ? ((u >> shift) & 0xFFu)
                                                   : 0xFFFFFFFFu;
            unsigned same = __match_any_sync(0xFFFFFFFFu, bin);
            if (bin != 0xFFFFFFFFu && lane == (__ffs(same) - 1))
                atomicAdd(&hist[bin], __popc(same));
        }
        __syncthreads();

        if (t == 0) {
            int k = s_k;
            int bin = 255;
            for (;;) {
                int c = (int)hist[bin];
                if (c >= k) break;
                k -= c;
                bin--;
            }
            s_prefix = prefix | ((unsigned)bin << shift);
            s_k = k;
        }
        __syncthreads();
    }

    if (t == 0) {
        d_thr[b] = s_prefix;     // exact key of the K-th largest value
        d_count[b] = 0;          // reset for next graph replay
        __threadfence();
    }
}

// ---------------------------------------------------------------------------
// Kernel 2: out = in * gate. One thread = 2 adjacent gate cells = one 32B
// sector (2 float4 in, 2 float4 out). Dead sector (both cells below thr):
// skip the input load entirely, write zeros. Live: __ldcs streaming loads.
// ---------------------------------------------------------------------------
__global__ void gate_mul_kernel(const float4* __restrict__ in,
                                float4* __restrict__ out) {
    int idx = blockIdx.x * blockDim.x + threadIdx.x;  // pair index, [0, 6291456)
    int x2 = idx & 63;             // pair col (2 gate cells)
    int y  = (idx >> 6) & 511;     // image row
    int bc = idx >> 15;            // b*3 + c
    int b  = bc / 3;

    unsigned thr = __ldg(&d_thr[b]);
    float2 g2 = *reinterpret_cast<const float2*>(
        &d_gate[b * 16384 + (y >> 2) * 128 + 2 * x2]);

    bool a0 = f2key(g2.x) >= thr;
    bool a1 = f2key(g2.y) >= thr;

    int base = idx * 2;
    float4 v0 = make_float4(0.f, 0.f, 0.f, 0.f);
    float4 v1 = v0;
    if (a0 | a1) {
        float4 t0 = __ldcs(&in[base]);
        float4 t1 = __ldcs(&in[base + 1]);
        if (a0) { v0.x = t0.x * g2.x; v0.y = t0.y * g2.x;
                  v0.z = t0.z * g2.x; v0.w = t0.w * g2.x; }
        if (a1) { v1.x = t1.x * g2.y; v1.y = t1.y * g2.y;
                  v1.z = t1.z * g2.y; v1.w = t1.w * g2.y; }
    }
    out[base]     = v0;
    out[base + 1] = v1;
}

// ---------------------------------------------------------------------------
extern "C" void kernel_launch(void* const* d_in, const int* in_sizes, int n_in,
                              void* d_out, int out_size) {
    const float* inp = (const float*)d_in[0];
    const float* wk  = (const float*)d_in[1];
    if (n_in >= 2 && in_sizes[0] == 48) {  // defensive: swap if order flipped
        inp = (const float*)d_in[1];
        wk  = (const float*)d_in[0];
    }

    gate_conv_select_kernel<<<4096, 256>>>((const float4*)inp, wk);
    // 64*3*512*64 sector-pairs / 256
    gate_mul_kernel<<<24576, 256>>>((const float4*)inp, (float4*)d_out);
}

// round 4
// speedup vs baseline: 1.1371x; 1.1371x over previous
#include <cuda_runtime.h>
#include <cstdint>

// Gate pipeline (3 kernels):
//   K1: conv 4x4/s4 [64,3,512,512] -> gate[64,128,128]
//   K2: per-batch exact K-th-largest key (radix select, atomic-free)
//   K3: out = in * (gate >= thr ? gate : 0), 4x upsample, 3ch bcast,
//       32B-sector-exact read skipping (~56% of read sectors dead)
__device__ float    d_gate[64 * 16384];
__device__ unsigned d_thr[64];

__device__ __forceinline__ unsigned f2key(float f) {
    unsigned u = __float_as_uint(f);
    return (u & 0x80000000u) ? ~u : (u | 0x80000000u);  // monotone float->uint
}

// ---------------------------------------------------------------------------
// Kernel 1: conv. One thread per gate pixel, 12 coalesced float4 loads.
// Measured 80% DRAM — at its traffic floor.
// ---------------------------------------------------------------------------
__global__ void gate_conv_kernel(const float4* __restrict__ in,
                                 const float* __restrict__ wk) {
    __shared__ float4 w[12];
    int t = threadIdx.x;
    if (t < 12) w[t] = reinterpret_cast<const float4*>(wk)[t];
    __syncthreads();

    int idx = blockIdx.x * blockDim.x + t;      // [0, 64*16384)
    int x = idx & 127;
    int y = (idx >> 7) & 127;
    int b = idx >> 14;

    const float4* base = in + (size_t)b * 196608 + x;
    float sum = 0.0f;
#pragma unroll
    for (int c = 0; c < 3; c++) {
#pragma unroll
        for (int i = 0; i < 4; i++) {
            float4 v = base[c * 65536 + (4 * y + i) * 128];
            float4 ww = w[c * 4 + i];
            sum += v.x * ww.x + v.y * ww.y + v.z * ww.z + v.w * ww.w;
        }
    }
    d_gate[idx] = sum;
}

// ---------------------------------------------------------------------------
// Kernel 2: per-batch K-th-largest key, MSB-first radix select, 4x8-bit.
// ATOMIC-FREE: warp-private histograms (match_any-aggregated leader updates)
// + parallel suffix-scan over the 256 bins. One block per batch, 512 thr.
// Gate reads are L2-hot (conv just wrote the 4MB).
// ---------------------------------------------------------------------------
__global__ void gate_select_kernel() {
    __shared__ unsigned hist[16][256];   // per-warp private
    __shared__ int suffix[256];
    __shared__ unsigned s_prefix;
    __shared__ int s_k;

    const int row = blockIdx.x;
    const int t = threadIdx.x;          // blockDim = 512
    const int warp = t >> 5;
    const int lane = t & 31;
    const float* grow = d_gate + row * 16384;

    if (t == 0) { s_prefix = 0u; s_k = 4096; }

#pragma unroll
    for (int pass = 0; pass < 4; pass++) {
        const int shift = 24 - 8 * pass;
        for (int i = t; i < 16 * 256; i += 512)
            (&hist[0][0])[i] = 0u;
        __syncthreads();

        const unsigned pmask = pass ? (0xFFFFFFFFu << (32 - 8 * pass)) : 0u;
        const unsigned prefix = s_prefix;

#pragma unroll
        for (int i = 0; i < 32; i++) {
            unsigned u = f2key(grow[t + i * 512]);
            unsigned bin = ((u & pmask) == prefix) ? ((u >> shift) & 0xFFu)
                                                   : 0xFFFFFFFFu;
            unsigned same = __match_any_sync(0xFFFFFFFFu, bin);
            if (bin != 0xFFFFFFFFu && lane == (__ffs(same) - 1))
                hist[warp][bin] += __popc(same);   // warp-private: no atomics
        }
        __syncthreads();

        // reduce 16 warp histograms -> suffix[bin]
        if (t < 256) {
            int c = 0;
#pragma unroll
            for (int wg = 0; wg < 16; wg++) c += hist[wg][t];
            suffix[t] = c;
        }
        __syncthreads();

        // parallel suffix sum: suffix[t] = sum_{j>=t} count[j]
#pragma unroll
        for (int off = 1; off < 256; off <<= 1) {
            int v = 0;
            if (t < 256 && t + off < 256) v = suffix[t + off];
            __syncthreads();
            if (t < 256) suffix[t] += v;
            __syncthreads();
        }

        // locate bin where cumulative-from-top first reaches k (unique t)
        const int kcur = s_k;
        int above = (t < 255) ? suffix[t + 1] : 0;
        __syncthreads();
        if (t < 256 && suffix[t] >= kcur && above < kcur) {
            s_prefix = prefix | ((unsigned)t << shift);
            s_k = kcur - above;
        }
        __syncthreads();
    }

    if (t == 0) d_thr[row] = s_prefix;   // exact key of K-th largest
}

// ---------------------------------------------------------------------------
// Kernel 3: out = in * gate. One thread = 4 gate cells (one float4 gate load)
// = 4 float4 = 64B of in/out = two independent 32B-sector skip decisions.
// ---------------------------------------------------------------------------
__global__ void gate_mul_kernel(const float4* __restrict__ in,
                                float4* __restrict__ out) {
    int idx = blockIdx.x * blockDim.x + threadIdx.x;  // [0, 64*3*512*32)
    int xg = idx & 31;             // group of 4 gate cells
    int y  = (idx >> 5) & 511;     // image row
    int bc = idx >> 14;            // b*3 + c
    int b  = bc / 3;

    unsigned thr = __ldg(&d_thr[b]);
    float4 g = *reinterpret_cast<const float4*>(
        &d_gate[b * 16384 + (y >> 2) * 128 + 4 * xg]);

    bool a0 = f2key(g.x) >= thr;
    bool a1 = f2key(g.y) >= thr;
    bool a2 = f2key(g.z) >= thr;
    bool a3 = f2key(g.w) >= thr;

    int base = idx * 4;
    float4 z = make_float4(0.f, 0.f, 0.f, 0.f);
    float4 v0 = z, v1 = z, v2 = z, v3 = z;

    if (a0 | a1) {                       // sector 0 live
        float4 t0 = __ldcs(&in[base]);
        float4 t1 = __ldcs(&in[base + 1]);
        if (a0) { v0.x = t0.x * g.x; v0.y = t0.y * g.x;
                  v0.z = t0.z * g.x; v0.w = t0.w * g.x; }
        if (a1) { v1.x = t1.x * g.y; v1.y = t1.y * g.y;
                  v1.z = t1.z * g.y; v1.w = t1.w * g.y; }
    }
    if (a2 | a3) {                       // sector 1 live
        float4 t2 = __ldcs(&in[base + 2]);
        float4 t3 = __ldcs(&in[base + 3]);
        if (a2) { v2.x = t2.x * g.z; v2.y = t2.y * g.z;
                  v2.z = t2.z * g.z; v2.w = t2.w * g.z; }
        if (a3) { v3.x = t3.x * g.w; v3.y = t3.y * g.w;
                  v3.z = t3.z * g.w; v3.w = t3.w * g.w; }
    }
    out[base]     = v0;
    out[base + 1] = v1;
    out[base + 2] = v2;
    out[base + 3] = v3;
}

// ---------------------------------------------------------------------------
extern "C" void kernel_launch(void* const* d_in, const int* in_sizes, int n_in,
                              void* d_out, int out_size) {
    const float* inp = (const float*)d_in[0];
    const float* wk  = (const float*)d_in[1];
    if (n_in >= 2 && in_sizes[0] == 48) {  // defensive: swap if order flipped
        inp = (const float*)d_in[1];
        wk  = (const float*)d_in[0];
    }

    gate_conv_kernel<<<4096, 256>>>((const float4*)inp, wk);
    gate_select_kernel<<<64, 512>>>();
    // 64*3*512*32 thread-groups / 256
    gate_mul_kernel<<<12288, 256>>>((const float4*)inp, (float4*)d_out);
}

// round 5
// speedup vs baseline: 1.1514x; 1.0126x over previous
#include <cuda_runtime.h>
#include <cstdint>

// Gate pipeline (3 kernels):
//   K1: conv 4x4/s4 [64,3,512,512] -> gate[64,128,128]
//   K2: per-batch exact K-th-largest key (radix select; keys in registers)
//   K3: out = in * (gate >= thr ? gate : 0), 4x upsample, 3ch bcast,
//       32B-sector-exact read skipping (~56% of read sectors dead)
__device__ float    d_gate[64 * 16384];
__device__ unsigned d_thr[64];

__device__ __forceinline__ unsigned f2key(float f) {
    unsigned u = __float_as_uint(f);
    return (u & 0x80000000u) ? ~u : (u | 0x80000000u);  // monotone float->uint
}

// ---------------------------------------------------------------------------
// Kernel 1: conv. One thread per gate pixel, 12 coalesced float4 loads.
// Measured 79-80% DRAM — at the read-stream ceiling.
// ---------------------------------------------------------------------------
__global__ void gate_conv_kernel(const float4* __restrict__ in,
                                 const float* __restrict__ wk) {
    __shared__ float4 w[12];
    int t = threadIdx.x;
    if (t < 12) w[t] = reinterpret_cast<const float4*>(wk)[t];
    __syncthreads();

    int idx = blockIdx.x * blockDim.x + t;      // [0, 64*16384)
    int x = idx & 127;
    int y = (idx >> 7) & 127;
    int b = idx >> 14;

    const float4* base = in + (size_t)b * 196608 + x;
    float sum = 0.0f;
#pragma unroll
    for (int c = 0; c < 3; c++) {
#pragma unroll
        for (int i = 0; i < 4; i++) {
            float4 v = base[c * 65536 + (4 * y + i) * 128];
            float4 ww = w[c * 4 + i];
            sum += v.x * ww.x + v.y * ww.y + v.z * ww.z + v.w * ww.w;
        }
    }
    d_gate[idx] = sum;
}

// ---------------------------------------------------------------------------
// Kernel 2: per-batch K-th-largest key, MSB-first radix select, 4x8-bit.
// Keys loaded into REGISTERS once (MLP=32, one latency exposure), then all
// 4 passes run register->smem only. Warp-private histograms (match_any
// leader updates, no atomics) + parallel suffix-scan of the 256 bins.
// One block per batch, 512 threads.
// ---------------------------------------------------------------------------
__global__ void __launch_bounds__(512) gate_select_kernel() {
    __shared__ unsigned hist[16][256];   // per-warp private
    __shared__ int suffix[256];
    __shared__ unsigned s_prefix;
    __shared__ int s_k;

    const int row = blockIdx.x;
    const int t = threadIdx.x;          // blockDim = 512
    const int warp = t >> 5;
    const int lane = t & 31;
    const float* grow = d_gate + row * 16384;

    // one-shot load: 32 independent L2-hot loads per thread
    unsigned key[32];
#pragma unroll
    for (int i = 0; i < 32; i++)
        key[i] = f2key(grow[t + i * 512]);

    if (t == 0) { s_prefix = 0u; s_k = 4096; }

#pragma unroll
    for (int pass = 0; pass < 4; pass++) {
        const int shift = 24 - 8 * pass;
        for (int i = t; i < 16 * 256; i += 512)
            (&hist[0][0])[i] = 0u;
        __syncthreads();

        const unsigned pmask = pass ? (0xFFFFFFFFu << (32 - 8 * pass)) : 0u;
        const unsigned prefix = s_prefix;

#pragma unroll
        for (int i = 0; i < 32; i++) {
            unsigned u = key[i];
            unsigned bin = ((u & pmask) == prefix) ? ((u >> shift) & 0xFFu)
                                                   : 0xFFFFFFFFu;
            unsigned same = __match_any_sync(0xFFFFFFFFu, bin);
            if (bin != 0xFFFFFFFFu && lane == (__ffs(same) - 1))
                hist[warp][bin] += __popc(same);   // warp-private: no atomics
        }
        __syncthreads();

        // reduce 16 warp histograms -> suffix[bin]
        if (t < 256) {
            int c = 0;
#pragma unroll
            for (int wg = 0; wg < 16; wg++) c += hist[wg][t];
            suffix[t] = c;
        }
        __syncthreads();

        // parallel suffix sum: suffix[t] = sum_{j>=t} count[j]
#pragma unroll
        for (int off = 1; off < 256; off <<= 1) {
            int v = 0;
            if (t < 256 && t + off < 256) v = suffix[t + off];
            __syncthreads();
            if (t < 256) suffix[t] += v;
            __syncthreads();
        }

        // locate bin where cumulative-from-top first reaches k (unique t)
        const int kcur = s_k;
        int above = (t < 255) ? suffix[t + 1] : 0;
        __syncthreads();
        if (t < 256 && suffix[t] >= kcur && above < kcur) {
            s_prefix = prefix | ((unsigned)t << shift);
            s_k = kcur - above;
        }
        __syncthreads();
    }

    if (t == 0) d_thr[row] = s_prefix;   // exact key of K-th largest
}

// ---------------------------------------------------------------------------
// Kernel 3: out = in * gate. One thread = 4 gate cells (one float4 gate load)
// = 4 float4 = 64B of in/out = two independent 32B-sector skip decisions.
// ---------------------------------------------------------------------------
__global__ void gate_mul_kernel(const float4* __restrict__ in,
                                float4* __restrict__ out) {
    int idx = blockIdx.x * blockDim.x + threadIdx.x;  // [0, 64*3*512*32)
    int xg = idx & 31;             // group of 4 gate cells
    int y  = (idx >> 5) & 511;     // image row
    int bc = idx >> 14;            // b*3 + c
    int b  = bc / 3;

    unsigned thr = __ldg(&d_thr[b]);
    float4 g = *reinterpret_cast<const float4*>(
        &d_gate[b * 16384 + (y >> 2) * 128 + 4 * xg]);

    bool a0 = f2key(g.x) >= thr;
    bool a1 = f2key(g.y) >= thr;
    bool a2 = f2key(g.z) >= thr;
    bool a3 = f2key(g.w) >= thr;

    int base = idx * 4;
    float4 z = make_float4(0.f, 0.f, 0.f, 0.f);
    float4 v0 = z, v1 = z, v2 = z, v3 = z;

    if (a0 | a1) {                       // sector 0 live
        float4 t0 = __ldcs(&in[base]);
        float4 t1 = __ldcs(&in[base + 1]);
        if (a0) { v0.x = t0.x * g.x; v0.y = t0.y * g.x;
                  v0.z = t0.z * g.x; v0.w = t0.w * g.x; }
        if (a1) { v1.x = t1.x * g.y; v1.y = t1.y * g.y;
                  v1.z = t1.z * g.y; v1.w = t1.w * g.y; }
    }
    if (a2 | a3) {                       // sector 1 live
        float4 t2 = __ldcs(&in[base + 2]);
        float4 t3 = __ldcs(&in[base + 3]);
        if (a2) { v2.x = t2.x * g.z; v2.y = t2.y * g.z;
                  v2.z = t2.z * g.z; v2.w = t2.w * g.z; }
        if (a3) { v3.x = t3.x * g.w; v3.y = t3.y * g.w;
                  v3.z = t3.z * g.w; v3.w = t3.w * g.w; }
    }
    out[base]     = v0;
    out[base + 1] = v1;
    out[base + 2] = v2;
    out[base + 3] = v3;
}

// ---------------------------------------------------------------------------
extern "C" void kernel_launch(void* const* d_in, const int* in_sizes, int n_in,
                              void* d_out, int out_size) {
    const float* inp = (const float*)d_in[0];
    const float* wk  = (const float*)d_in[1];
    if (n_in >= 2 && in_sizes[0] == 48) {  // defensive: swap if order flipped
        inp = (const float*)d_in[1];
        wk  = (const float*)d_in[0];
    }

    gate_conv_kernel<<<4096, 256>>>((const float4*)inp, wk);
    gate_select_kernel<<<64, 512>>>();
    // 64*3*512*32 thread-groups / 256
    gate_mul_kernel<<<12288, 256>>>((const float4*)inp, (float4*)d_out);
}

// round 6
// speedup vs baseline: 1.1750x; 1.0205x over previous
#include <cuda_runtime.h>
#include <cstdint>

// Gate pipeline (3 kernels):
//   K1: conv 4x4/s4 [64,3,512,512] -> gate[64,128,128]
//   K2: per-batch exact K-th-largest key (radix select; keys in registers)
//   K3: out = in * (gate >= thr ? gate : 0), 4x upsample, 3ch bcast.
//       Fully coalesced 16B/lane; predicated loads skip dead 32B sectors.
__device__ float    d_gate[64 * 16384];
__device__ unsigned d_thr[64];

__device__ __forceinline__ unsigned f2key(float f) {
    unsigned u = __float_as_uint(f);
    return (u & 0x80000000u) ? ~u : (u | 0x80000000u);  // monotone float->uint
}

// ---------------------------------------------------------------------------
// Kernel 1: conv. One thread per gate pixel, 12 coalesced float4 loads.
// Measured 76-80% DRAM — at the read-stream ceiling.
// ---------------------------------------------------------------------------
__global__ void gate_conv_kernel(const float4* __restrict__ in,
                                 const float* __restrict__ wk) {
    __shared__ float4 w[12];
    int t = threadIdx.x;
    if (t < 12) w[t] = reinterpret_cast<const float4*>(wk)[t];
    __syncthreads();

    int idx = blockIdx.x * blockDim.x + t;      // [0, 64*16384)
    int x = idx & 127;
    int y = (idx >> 7) & 127;
    int b = idx >> 14;

    const float4* base = in + (size_t)b * 196608 + x;
    float sum = 0.0f;
#pragma unroll
    for (int c = 0; c < 3; c++) {
#pragma unroll
        for (int i = 0; i < 4; i++) {
            float4 v = base[c * 65536 + (4 * y + i) * 128];
            float4 ww = w[c * 4 + i];
            sum += v.x * ww.x + v.y * ww.y + v.z * ww.z + v.w * ww.w;
        }
    }
    d_gate[idx] = sum;
}

// ---------------------------------------------------------------------------
// Kernel 2: per-batch K-th-largest key, MSB-first radix select, 4x8-bit.
// Keys register-resident (one latency exposure, MLP=32); warp-private
// histograms (match_any leader updates, no atomics); parallel suffix-scan.
// One block per batch, 512 threads. ~4-6us total.
// ---------------------------------------------------------------------------
__global__ void __launch_bounds__(512) gate_select_kernel() {
    __shared__ unsigned hist[16][256];   // per-warp private
    __shared__ int suffix[256];
    __shared__ unsigned s_prefix;
    __shared__ int s_k;

    const int row = blockIdx.x;
    const int t = threadIdx.x;          // blockDim = 512
    const int warp = t >> 5;
    const int lane = t & 31;
    const float* grow = d_gate + row * 16384;

    unsigned key[32];
#pragma unroll
    for (int i = 0; i < 32; i++)
        key[i] = f2key(grow[t + i * 512]);

    if (t == 0) { s_prefix = 0u; s_k = 4096; }

#pragma unroll
    for (int pass = 0; pass < 4; pass++) {
        const int shift = 24 - 8 * pass;
        for (int i = t; i < 16 * 256; i += 512)
            (&hist[0][0])[i] = 0u;
        __syncthreads();

        const unsigned pmask = pass ? (0xFFFFFFFFu << (32 - 8 * pass)) : 0u;
        const unsigned prefix = s_prefix;

#pragma unroll
        for (int i = 0; i < 32; i++) {
            unsigned u = key[i];
            unsigned bin = ((u & pmask) == prefix) ? ((u >> shift) & 0xFFu)
                                                   : 0xFFFFFFFFu;
            unsigned same = __match_any_sync(0xFFFFFFFFu, bin);
            if (bin != 0xFFFFFFFFu && lane == (__ffs(same) - 1))
                hist[warp][bin] += __popc(same);   // warp-private: no atomics
        }
        __syncthreads();

        if (t < 256) {
            int c = 0;
#pragma unroll
            for (int wg = 0; wg < 16; wg++) c += hist[wg][t];
            suffix[t] = c;
        }
        __syncthreads();

#pragma unroll
        for (int off = 1; off < 256; off <<= 1) {
            int v = 0;
            if (t < 256 && t + off < 256) v = suffix[t + off];
            __syncthreads();
            if (t < 256) suffix[t] += v;
            __syncthreads();
        }

        const int kcur = s_k;
        int above = (t < 255) ? suffix[t + 1] : 0;
        __syncthreads();
        if (t < 256 && suffix[t] >= kcur && above < kcur) {
            s_prefix = prefix | ((unsigned)t << shift);
            s_k = kcur - above;
        }
        __syncthreads();
    }

    if (t == 0) d_thr[row] = s_prefix;   // exact key of K-th largest
}

// ---------------------------------------------------------------------------
// Kernel 3: out = in * gate. One thread = ONE float4 (16B): warp accesses are
// perfectly contiguous 2048B per instruction. Dead gate cell -> predicated-off
// load (HW fetches only sectors with >=1 live lane: exact 32B skipping).
// blockIdx.y = batch (no integer division anywhere).
// ---------------------------------------------------------------------------
__global__ void gate_mul_kernel(const float4* __restrict__ in,
                                float4* __restrict__ out) {
    int i  = blockIdx.x * blockDim.x + threadIdx.x;  // [0, 3*512*128)
    int b  = blockIdx.y;
    int x4 = i & 127;              // float4 col == gate col
    int y  = (i >> 7) & 511;       // image row  (c = i >> 16, unused)

    unsigned thr = __ldg(&d_thr[b]);
    float gv = d_gate[b * 16384 + (y >> 2) * 128 + x4];

    size_t idx = (size_t)b * 196608 + i;
    float4 v = make_float4(0.f, 0.f, 0.f, 0.f);
    if (f2key(gv) >= thr) {
        v = in[idx];
        v.x *= gv; v.y *= gv; v.z *= gv; v.w *= gv;
    }
    out[idx] = v;
}

// ---------------------------------------------------------------------------
extern "C" void kernel_launch(void* const* d_in, const int* in_sizes, int n_in,
                              void* d_out, int out_size) {
    const float* inp = (const float*)d_in[0];
    const float* wk  = (const float*)d_in[1];
    if (n_in >= 2 && in_sizes[0] == 48) {  // defensive: swap if order flipped
        inp = (const float*)d_in[1];
        wk  = (const float*)d_in[0];
    }

    gate_conv_kernel<<<4096, 256>>>((const float4*)inp, wk);
    gate_select_kernel<<<64, 512>>>();
    // per batch: 3*512*128 float4 / 256 = 768 blocks
    dim3 mgrid(768, 64);
    gate_mul_kernel<<<mgrid, 256>>>((const float4*)inp, (float4*)d_out);
}

// round 7
// speedup vs baseline: 1.3266x; 1.1290x over previous
#include <cuda_runtime.h>
#include <cstdint>

// Gate pipeline (3 kernels):
//   K1: conv 4x4/s4 [64,3,512,512] -> gate[64,128,128]
//   K2: per-batch exact K-th-largest key (radix select, low-barrier)
//   K3: out = in * (gate >= thr ? gate : 0), 4x upsample, 3ch bcast.
//       One thread = 1 gate cell x 4 rows: MLP=4, sector-exact read skip.
__device__ float    d_gate[64 * 16384];
__device__ unsigned d_thr[64];

__device__ __forceinline__ unsigned f2key(float f) {
    unsigned u = __float_as_uint(f);
    return (u & 0x80000000u) ? ~u : (u | 0x80000000u);  // monotone float->uint
}

// ---------------------------------------------------------------------------
// Kernel 1: conv. One thread per gate pixel, 12 coalesced float4 loads.
// Measured 79-80% DRAM — at the read-stream ceiling.
// ---------------------------------------------------------------------------
__global__ void gate_conv_kernel(const float4* __restrict__ in,
                                 const float* __restrict__ wk) {
    __shared__ float4 w[12];
    int t = threadIdx.x;
    if (t < 12) w[t] = reinterpret_cast<const float4*>(wk)[t];
    __syncthreads();

    int idx = blockIdx.x * blockDim.x + t;      // [0, 64*16384)
    int x = idx & 127;
    int y = (idx >> 7) & 127;
    int b = idx >> 14;

    const float4* base = in + (size_t)b * 196608 + x;
    float sum = 0.0f;
#pragma unroll
    for (int c = 0; c < 3; c++) {
#pragma unroll
        for (int i = 0; i < 4; i++) {
            float4 v = base[c * 65536 + (4 * y + i) * 128];
            float4 ww = w[c * 4 + i];
            sum += v.x * ww.x + v.y * ww.y + v.z * ww.z + v.w * ww.w;
        }
    }
    d_gate[idx] = sum;
}

// ---------------------------------------------------------------------------
// Kernel 2: per-batch K-th-largest key, MSB-first radix select, 4x8-bit.
// Register-resident keys (float4 loads); warp-private histograms (match_any
// leader updates, no atomics); SINGLE-WARP suffix scan (shfl) -> only 4
// __syncthreads per pass. One block per batch, 512 threads.
// ---------------------------------------------------------------------------
__global__ void __launch_bounds__(512) gate_select_kernel() {
    __shared__ unsigned hist[16][256];   // per-warp private
    __shared__ int cnt[256];
    __shared__ unsigned s_prefix;
    __shared__ int s_k;

    const int row = blockIdx.x;
    const int t = threadIdx.x;          // blockDim = 512
    const int warp = t >> 5;
    const int lane = t & 31;

    // vectorized one-shot key load: 8 float4 = 32 keys per thread
    unsigned key[32];
    const float4* g4 = reinterpret_cast<const float4*>(d_gate + row * 16384);
#pragma unroll
    for (int i = 0; i < 8; i++) {
        float4 v = g4[t + i * 512];
        key[4 * i + 0] = f2key(v.x);
        key[4 * i + 1] = f2key(v.y);
        key[4 * i + 2] = f2key(v.z);
        key[4 * i + 3] = f2key(v.w);
    }

    if (t == 0) { s_prefix = 0u; s_k = 4096; }

#pragma unroll
    for (int pass = 0; pass < 4; pass++) {
        const int shift = 24 - 8 * pass;
        for (int i = t; i < 16 * 256; i += 512)
            (&hist[0][0])[i] = 0u;
        __syncthreads();                               // barrier 1

        const unsigned pmask = pass ? (0xFFFFFFFFu << (32 - 8 * pass)) : 0u;
        const unsigned prefix = s_prefix;
        const int kcur = s_k;

#pragma unroll
        for (int i = 0; i < 32; i++) {
            unsigned u = key[i];
            unsigned bin = ((u & pmask) == prefix) ? ((u >> shift) & 0xFFu)
                                                   : 0xFFFFFFFFu;
            unsigned same = __match_any_sync(0xFFFFFFFFu, bin);
            if (bin != 0xFFFFFFFFu && lane == (__ffs(same) - 1))
                hist[warp][bin] += __popc(same);       // warp-private
        }
        __syncthreads();                               // barrier 2

        if (t < 256) {
            int c = 0;
#pragma unroll
            for (int wg = 0; wg < 16; wg++) c += hist[wg][t];
            cnt[t] = c;
        }
        __syncthreads();                               // barrier 3

        // warp 0: suffix scan over 256 bins (8 bins per lane) + pick bin
        if (warp == 0) {
            int v[8], s[8];
#pragma unroll
            for (int j = 0; j < 8; j++) v[j] = cnt[lane * 8 + j];
            s[7] = v[7];
#pragma unroll
            for (int j = 6; j >= 0; j--) s[j] = s[j + 1] + v[j];
            // suffix over lane totals
            int suf = s[0];
#pragma unroll
            for (int off = 1; off < 32; off <<= 1) {
                int o = __shfl_down_sync(0xFFFFFFFFu, suf, off);
                if (lane + off < 32) suf += o;
            }
            int above_lanes = suf - s[0];   // sum over lanes > lane
#pragma unroll
            for (int j = 0; j < 8; j++) {
                int Sj = s[j] + above_lanes;
                int Sn = (j < 7 ? s[j + 1] : 0) + above_lanes;
                if (Sj >= kcur && Sn < kcur) {   // exactly one (lane,j) hits
                    s_prefix = prefix | ((unsigned)(lane * 8 + j) << shift);
                    s_k = kcur - Sn;
                }
            }
        }
        __syncthreads();                               // barrier 4
    }

    if (t == 0) d_thr[row] = s_prefix;   // exact key of K-th largest
}

// ---------------------------------------------------------------------------
// Kernel 3: out = in * gate. One thread = one gate cell x 4 image rows:
// 1 gate load, 4 INDEPENDENT in loads (MLP=4, predicated off when dead),
// 4 stores. Warp per-instruction access = contiguous 512B. No int division.
// ---------------------------------------------------------------------------
__global__ void gate_mul_kernel(const float4* __restrict__ in,
                                float4* __restrict__ out) {
    int i  = blockIdx.x * blockDim.x + threadIdx.x;  // [0, 128*128)
    int x4 = i & 127;              // float4 col == gate col
    int gy = i >> 7;               // gate row
    int c  = blockIdx.y;           // channel
    int b  = blockIdx.z;           // batch

    unsigned thr = __ldg(&d_thr[b]);
    float gv = d_gate[b * 16384 + gy * 128 + x4];
    bool alive = f2key(gv) >= thr;

    size_t base = (size_t)(b * 3 + c) * 65536 + (size_t)(4 * gy) * 128 + x4;

    float4 z = make_float4(0.f, 0.f, 0.f, 0.f);
    float4 v0 = z, v1 = z, v2 = z, v3 = z;
    if (alive) {
        float4 t0 = in[base];
        float4 t1 = in[base + 128];
        float4 t2 = in[base + 256];
        float4 t3 = in[base + 384];
        v0.x = t0.x * gv; v0.y = t0.y * gv; v0.z = t0.z * gv; v0.w = t0.w * gv;
        v1.x = t1.x * gv; v1.y = t1.y * gv; v1.z = t1.z * gv; v1.w = t1.w * gv;
        v2.x = t2.x * gv; v2.y = t2.y * gv; v2.z = t2.z * gv; v2.w = t2.w * gv;
        v3.x = t3.x * gv; v3.y = t3.y * gv; v3.z = t3.z * gv; v3.w = t3.w * gv;
    }
    out[base]       = v0;
    out[base + 128] = v1;
    out[base + 256] = v2;
    out[base + 384] = v3;
}

// ---------------------------------------------------------------------------
extern "C" void kernel_launch(void* const* d_in, const int* in_sizes, int n_in,
                              void* d_out, int out_size) {
    const float* inp = (const float*)d_in[0];
    const float* wk  = (const float*)d_in[1];
    if (n_in >= 2 && in_sizes[0] == 48) {  // defensive: swap if order flipped
        inp = (const float*)d_in[1];
        wk  = (const float*)d_in[0];
    }

    gate_conv_kernel<<<4096, 256>>>((const float4*)inp, wk);
    gate_select_kernel<<<64, 512>>>();
    // 128*128 gate cells / 256 = 64 blocks; y = 3 channels; z = 64 batches
    dim3 mgrid(64, 3, 64);
    gate_mul_kernel<<<mgrid, 256>>>((const float4*)inp, (float4*)d_out);
}